// round 13
// baseline (speedup 1.0000x reference)
#include <cuda_runtime.h>
#include <cuda_bf16.h>
#include <math.h>

// Shapes: x, mix: [8,192,64,64] fp32 ; W: [191,192] ; b: [191]
// Outputs: ybar then mix_out, each 6291456 floats, contiguous in d_out.
#define CCH   192
#define TT    16
#define NTIL  12
#define BLOCK 256              // 256 threads, 1 pixel/thread -> 8 warps/SM
#define NPIX  32768
#define NCHW  6291456
#define ACC_STRIDE 98          // u64 per thread: 784 B = 16*49 -> 16B-aligned rows,
                               // conflict-free LDS.128 (lane stride 4 banks x 8 lanes)

typedef unsigned long long u64;

__device__ __forceinline__ u64 pack2(float a, float b) {
    u64 r; asm("mov.b64 %0, {%1,%2};" : "=l"(r) : "f"(a), "f"(b)); return r;
}
__device__ __forceinline__ void unpack2(u64 v, float& a, float& b) {
    asm("mov.b64 {%0,%1}, %2;" : "=f"(a), "=f"(b) : "l"(v));
}
__device__ __forceinline__ u64 fma2(u64 a, u64 b, u64 c) {
    u64 d; asm("fma.rn.f32x2 %0, %1, %2, %3;" : "=l"(d) : "l"(a), "l"(b), "l"(c)); return d;
}
__device__ __forceinline__ u64 add2(u64 a, u64 b) {
    u64 d; asm("add.rn.f32x2 %0, %1, %2;" : "=l"(d) : "l"(a), "l"(b)); return d;
}

// smem: acc 256*98*8 = 200704 B, Wx 88*16*8 = 11264 B, Ws 240*4, bs 191*4
//       -> 213692 B (~208.7 KB) < 227 KB
__global__ void __launch_bounds__(BLOCK, 1)
chan_deps_kernel(const float* __restrict__ x,
                 const float* __restrict__ mix,
                 const float* __restrict__ W,
                 const float* __restrict__ b,
                 float* __restrict__ ybar_out,
                 float* __restrict__ mix_out)
{
    extern __shared__ char smem_raw[];
    u64*   acc = reinterpret_cast<u64*>(smem_raw);      // [256][98]
    u64*   Wx  = acc + BLOCK * ACC_STRIDE;              // 88*16 channel-pair u64
    float* Ws  = reinterpret_cast<float*>(Wx + 88 * TT);// 240 tri floats
    float* bs  = Ws + 240;                              // 191 bias

    const int tid  = threadIdx.x;
    const int p    = blockIdx.x * BLOCK + tid;          // one pixel per thread
    const int base = (((p >> 12) * CCH) << 12) + (p & 4095);

    u64* accp = acc + tid * ACC_STRIDE;

    // zero accumulators: accp[k] = (acc[2k], acc[2k+1]) for this pixel
    #pragma unroll 8
    for (int k = 0; k < CCH / 2; k++) accp[k] = 0ull;

    if (tid < CCH - 1) bs[tid] = __ldg(&b[tid]);

    // ---- stage tile-0 slabs directly ----
    for (int k = tid; k < 88 * 4; k += BLOCK) {
        const int pr = k >> 2, q = k & 3, c2 = TT + 2 * pr, col = 4 * q;
        const float4 a4 = __ldg(reinterpret_cast<const float4*>(W + (c2 - 1) * CCH + col));
        const float4 b4 = __ldg(reinterpret_cast<const float4*>(W + c2 * CCH + col));
        ulonglong2* dst = reinterpret_cast<ulonglong2*>(Wx + pr * TT + col);
        dst[0] = make_ulonglong2(pack2(a4.x, b4.x), pack2(a4.y, b4.y));
        dst[1] = make_ulonglong2(pack2(a4.z, b4.z), pack2(a4.w, b4.w));
    }
    if (tid < 240) Ws[tid] = __ldg(&W[(tid >> 4) * CCH + (tid & 15)]);
    __syncthreads();

    // ---- prefetch tile-1 slabs into registers ----
    float4 wa[2], wb[2];
    float  tv;
    {
        const int cb = TT, ce = 2 * TT, tasks = (88 - 8) * 4;   // 320
        #pragma unroll
        for (int k2 = 0; k2 < 2; k2++) {
            const int task = tid + k2 * BLOCK;
            if (task < tasks) {
                const int pr = task >> 2, q = task & 3, c2 = ce + 2 * pr;
                wa[k2] = __ldg(reinterpret_cast<const float4*>(W + (c2 - 1) * CCH + cb + 4 * q));
                wb[k2] = __ldg(reinterpret_cast<const float4*>(W + c2 * CCH + cb + 4 * q));
            }
        }
        if (tid < 240) tv = __ldg(&W[(cb + (tid >> 4)) * CCH + cb + (tid & 15)]);
    }

    for (int t = 0; t < NTIL; t++) {
        const int cbase = t * TT;
        const int cend  = cbase + TT;
        const int pairs = 88 - 8 * t;               // even; 0 at t=11

        // ---- load x/mix for my pixel, this channel tile
        float xv[TT], mv[TT];
        #pragma unroll
        for (int i = 0; i < TT; i++) {
            const int gi = base + ((cbase + i) << 12);
            xv[i] = __ldg(&x[gi]);
            mv[i] = __ldg(&mix[gi]);
        }

        // ---- sequential in-tile recurrence
        float part[TT];
        #pragma unroll
        for (int i = 0; i < TT; i++) part[i] = 0.f;

        u64 yd[TT];
        float aLo = 0.f, aHi = 0.f;
        #pragma unroll
        for (int i = 0; i < TT; i++) {
            const int c = cbase + i;
            if ((i & 1) == 0) unpack2(accp[c >> 1], aLo, aHi);   // LDS.64
            float m;
            if (i == 0 && t == 0) {                 // channel 0: no conv/bias
                m = mv[0];
            } else {
                const float a = (i & 1) ? aHi : aLo;
                m = a + bs[c - 1] + mv[i] + part[i];
            }
            const float y = rintf(xv[i] - m) + m;   // half-to-even = jnp.round
            yd[i] = pack2(y, y);
            const int gi = base + (c << 12);
            ybar_out[gi] = y;
            mix_out[gi]  = m;
            #pragma unroll
            for (int i2 = i + 1; i2 < TT; i2++)
                part[i2] = fmaf(Ws[(i2 - 1) * TT + i], y, part[i2]);
        }

        // ---- cross-tile rank-16 update: FFMA2 over channel pairs
        const int kb = cend >> 1;                   // even -> 16B-aligned acc pairs
        for (int pr = 0; pr < pairs; pr += 2) {
            const ulonglong2* wpA = reinterpret_cast<const ulonglong2*>(Wx + (pr << 4));
            const ulonglong2* wpB = reinterpret_cast<const ulonglong2*>(Wx + ((pr + 1) << 4));
            u64 sA = 0, sB = 0;
            #pragma unroll
            for (int h = 0; h < 8; h++) {
                const ulonglong2 A = wpA[h];
                sA = fma2(A.x, yd[2 * h], sA);
                sA = fma2(A.y, yd[2 * h + 1], sA);
                const ulonglong2 B = wpB[h];
                sB = fma2(B.x, yd[2 * h], sB);
                sB = fma2(B.y, yd[2 * h + 1], sB);
            }
            ulonglong2* ap = reinterpret_cast<ulonglong2*>(accp + kb + pr);
            ulonglong2 a = *ap;                     // LDS.128, conflict-free
            a.x = add2(a.x, sA);
            a.y = add2(a.y, sB);
            *ap = a;                                // STS.128
        }

        // ---- stage slabs for t+1 from regs, prefetch t+2
        if (t + 1 < NTIL) {
            __syncthreads();
            const int tasks1 = (88 - 8 * (t + 1)) * 4;
            #pragma unroll
            for (int k2 = 0; k2 < 2; k2++) {
                const int task = tid + k2 * BLOCK;
                if (task < tasks1) {
                    const int pr = task >> 2, q = task & 3;
                    ulonglong2* dst = reinterpret_cast<ulonglong2*>(Wx + pr * TT + 4 * q);
                    dst[0] = make_ulonglong2(pack2(wa[k2].x, wb[k2].x), pack2(wa[k2].y, wb[k2].y));
                    dst[1] = make_ulonglong2(pack2(wa[k2].z, wb[k2].z), pack2(wa[k2].w, wb[k2].w));
                }
            }
            if (tid < 240) Ws[tid] = tv;
            __syncthreads();

            if (t + 2 < NTIL) {
                const int cb2 = (t + 2) * TT, ce2 = cb2 + TT;
                const int tasks2 = (88 - 8 * (t + 2)) * 4;
                #pragma unroll
                for (int k2 = 0; k2 < 2; k2++) {
                    const int task = tid + k2 * BLOCK;
                    if (task < tasks2) {
                        const int pr = task >> 2, q = task & 3, c2 = ce2 + 2 * pr;
                        wa[k2] = __ldg(reinterpret_cast<const float4*>(W + (c2 - 1) * CCH + cb2 + 4 * q));
                        wb[k2] = __ldg(reinterpret_cast<const float4*>(W + c2 * CCH + cb2 + 4 * q));
                    }
                }
                if (tid < 240)
                    tv = __ldg(&W[(cb2 + (tid >> 4)) * CCH + cb2 + (tid & 15)]);
            }
        }
    }
}

extern "C" void kernel_launch(void* const* d_in, const int* in_sizes, int n_in,
                              void* d_out, int out_size)
{
    const float* x   = (const float*)d_in[0];
    const float* mix = (const float*)d_in[1];
    const float* W   = (const float*)d_in[2];
    const float* b   = (const float*)d_in[3];

    float* ybar_out = (float*)d_out;
    float* mix_out  = (float*)d_out + NCHW;

    const size_t smem_bytes = (size_t)(BLOCK * ACC_STRIDE + 88 * TT) * sizeof(u64)
                            + (240 + 191) * sizeof(float);
    cudaFuncSetAttribute(chan_deps_kernel,
                         cudaFuncAttributeMaxDynamicSharedMemorySize,
                         (int)smem_bytes);

    const int grid = NPIX / BLOCK;               // 128, single balanced wave
    chan_deps_kernel<<<grid, BLOCK, smem_bytes>>>(x, mix, W, b, ybar_out, mix_out);
}

// round 14
// speedup vs baseline: 1.0004x; 1.0004x over previous
#include <cuda_runtime.h>
#include <cuda_bf16.h>
#include <math.h>

// Shapes: x, mix: [8,192,64,64] fp32 ; W: [191,192] ; b: [191]
// Outputs: ybar then mix_out, each 6291456 floats, contiguous in d_out.
#define CCH   192
#define TT    16
#define NTIL  12
#define BLOCK 256              // 256 threads, 1 pixel/thread -> 8 warps/SM
#define NPIX  32768
#define NCHW  6291456
#define ACC_STRIDE 98          // u64/thread: 784B = 16*49 -> 16B-aligned, conflict-free

typedef unsigned long long u64;

__device__ __forceinline__ u64 pack2(float a, float b) {
    u64 r; asm("mov.b64 %0, {%1,%2};" : "=l"(r) : "f"(a), "f"(b)); return r;
}
__device__ __forceinline__ void unpack2(u64 v, float& a, float& b) {
    asm("mov.b64 {%0,%1}, %2;" : "=f"(a), "=f"(b) : "l"(v));
}
__device__ __forceinline__ u64 fma2(u64 a, u64 b, u64 c) {
    u64 d; asm("fma.rn.f32x2 %0, %1, %2, %3;" : "=l"(d) : "l"(a), "l"(b), "l"(c)); return d;
}
__device__ __forceinline__ u64 add2(u64 a, u64 b) {
    u64 d; asm("add.rn.f32x2 %0, %1, %2;" : "=l"(d) : "l"(a), "l"(b)); return d;
}

// smem: acc 256*98*8 = 200704 B, Wx 88*16*8 = 11264 B, Ws 240*4, bs 191*4 -> ~208.7 KB
__global__ void __launch_bounds__(BLOCK, 1)
chan_deps_kernel(const float* __restrict__ x,
                 const float* __restrict__ mix,
                 const float* __restrict__ W,
                 const float* __restrict__ b,
                 float* __restrict__ ybar_out,
                 float* __restrict__ mix_out)
{
    extern __shared__ char smem_raw[];
    u64*   acc = reinterpret_cast<u64*>(smem_raw);       // [256][98]
    u64*   Wx  = acc + BLOCK * ACC_STRIDE;               // 88*16 channel-pair u64
    float* Ws  = reinterpret_cast<float*>(Wx + 88 * TT); // 240 tri floats
    float* bs  = Ws + 240;                               // 191 bias

    const int tid  = threadIdx.x;
    const int p    = blockIdx.x * BLOCK + tid;           // one pixel per thread
    const int base = (((p >> 12) * CCH) << 12) + (p & 4095);

    u64* accp = acc + tid * ACC_STRIDE;

    #pragma unroll 8
    for (int k = 0; k < CCH / 2; k++) accp[k] = 0ull;

    if (tid < CCH - 1) bs[tid] = __ldg(&b[tid]);

    // ---- stage tile-0 slabs directly ----
    for (int k = tid; k < 88 * 4; k += BLOCK) {
        const int pr = k >> 2, q = k & 3, c2 = TT + 2 * pr, col = 4 * q;
        const float4 a4 = __ldg(reinterpret_cast<const float4*>(W + (c2 - 1) * CCH + col));
        const float4 b4 = __ldg(reinterpret_cast<const float4*>(W + c2 * CCH + col));
        ulonglong2* dst = reinterpret_cast<ulonglong2*>(Wx + pr * TT + col);
        dst[0] = make_ulonglong2(pack2(a4.x, b4.x), pack2(a4.y, b4.y));
        dst[1] = make_ulonglong2(pack2(a4.z, b4.z), pack2(a4.w, b4.w));
    }
    if (tid < 240) Ws[tid] = __ldg(&W[(tid >> 4) * CCH + (tid & 15)]);
    __syncthreads();

    // ---- prefetch tile-1 slabs into registers ----
    float4 wa[2], wb[2];
    float  tv;
    {
        const int cb = TT, ce = 2 * TT, tasks = (88 - 8) * 4;   // 320
        #pragma unroll
        for (int k2 = 0; k2 < 2; k2++) {
            const int task = tid + k2 * BLOCK;
            if (task < tasks) {
                const int pr = task >> 2, q = task & 3, c2 = ce + 2 * pr;
                wa[k2] = __ldg(reinterpret_cast<const float4*>(W + (c2 - 1) * CCH + cb + 4 * q));
                wb[k2] = __ldg(reinterpret_cast<const float4*>(W + c2 * CCH + cb + 4 * q));
            }
        }
        if (tid < 240) tv = __ldg(&W[(cb + (tid >> 4)) * CCH + cb + (tid & 15)]);
    }

    for (int t = 0; t < NTIL; t++) {
        const int cbase = t * TT;
        const int cend  = cbase + TT;
        const int pairs = 88 - 8 * t;               // multiple of 8; 0 at t=11

        // ---- load x/mix for my pixel, this channel tile
        float xv[TT], mv[TT];
        #pragma unroll
        for (int i = 0; i < TT; i++) {
            const int gi = base + ((cbase + i) << 12);
            xv[i] = __ldg(&x[gi]);
            mv[i] = __ldg(&mix[gi]);
        }

        // ---- sequential in-tile recurrence
        float part[TT];
        #pragma unroll
        for (int i = 0; i < TT; i++) part[i] = 0.f;

        u64 yd[TT];
        float aLo = 0.f, aHi = 0.f;
        #pragma unroll
        for (int i = 0; i < TT; i++) {
            const int c = cbase + i;
            if ((i & 1) == 0) unpack2(accp[c >> 1], aLo, aHi);   // LDS.64
            float m;
            if (i == 0 && t == 0) {                 // channel 0: no conv/bias
                m = mv[0];
            } else {
                const float a = (i & 1) ? aHi : aLo;
                m = a + bs[c - 1] + mv[i] + part[i];
            }
            const float y = rintf(xv[i] - m) + m;   // half-to-even = jnp.round
            yd[i] = pack2(y, y);
            const int gi = base + (c << 12);
            ybar_out[gi] = y;
            mix_out[gi]  = m;
            #pragma unroll
            for (int i2 = i + 1; i2 < TT; i2++)
                part[i2] = fmaf(Ws[(i2 - 1) * TT + i], y, part[i2]);
        }

        // ---- cross-tile rank-16 update: 4 channel-pair rows per iteration,
        //      each row's dot split into 2 partial chains -> 8 independent
        //      FFMA2 chains of depth 8 (was 2 chains of depth 16).
        const int kb = cend >> 1;                   // even -> 16B-aligned acc pairs
        for (int pr = 0; pr < pairs; pr += 4) {
            const ulonglong2* w0 = reinterpret_cast<const ulonglong2*>(Wx + ((pr + 0) << 4));
            const ulonglong2* w1 = reinterpret_cast<const ulonglong2*>(Wx + ((pr + 1) << 4));
            const ulonglong2* w2 = reinterpret_cast<const ulonglong2*>(Wx + ((pr + 2) << 4));
            const ulonglong2* w3 = reinterpret_cast<const ulonglong2*>(Wx + ((pr + 3) << 4));
            u64 s0e = 0, s0o = 0, s1e = 0, s1o = 0;
            u64 s2e = 0, s2o = 0, s3e = 0, s3o = 0;
            #pragma unroll
            for (int h = 0; h < 4; h++) {           // 2 ulonglong2 per row per step
                const ulonglong2 A0 = w0[2 * h],     A1 = w0[2 * h + 1];
                s0e = fma2(A0.x, yd[4 * h],     s0e); s0e = fma2(A0.y, yd[4 * h + 1], s0e);
                s0o = fma2(A1.x, yd[4 * h + 2], s0o); s0o = fma2(A1.y, yd[4 * h + 3], s0o);
                const ulonglong2 B0 = w1[2 * h],     B1 = w1[2 * h + 1];
                s1e = fma2(B0.x, yd[4 * h],     s1e); s1e = fma2(B0.y, yd[4 * h + 1], s1e);
                s1o = fma2(B1.x, yd[4 * h + 2], s1o); s1o = fma2(B1.y, yd[4 * h + 3], s1o);
                const ulonglong2 C0 = w2[2 * h],     C1 = w2[2 * h + 1];
                s2e = fma2(C0.x, yd[4 * h],     s2e); s2e = fma2(C0.y, yd[4 * h + 1], s2e);
                s2o = fma2(C1.x, yd[4 * h + 2], s2o); s2o = fma2(C1.y, yd[4 * h + 3], s2o);
                const ulonglong2 D0 = w3[2 * h],     D1 = w3[2 * h + 1];
                s3e = fma2(D0.x, yd[4 * h],     s3e); s3e = fma2(D0.y, yd[4 * h + 1], s3e);
                s3o = fma2(D1.x, yd[4 * h + 2], s3o); s3o = fma2(D1.y, yd[4 * h + 3], s3o);
            }
            ulonglong2* apA = reinterpret_cast<ulonglong2*>(accp + kb + pr);
            ulonglong2* apB = apA + 1;
            ulonglong2 aA = *apA;                   // LDS.128, conflict-free
            ulonglong2 aB = *apB;
            aA.x = add2(aA.x, add2(s0e, s0o));
            aA.y = add2(aA.y, add2(s1e, s1o));
            aB.x = add2(aB.x, add2(s2e, s2o));
            aB.y = add2(aB.y, add2(s3e, s3o));
            *apA = aA;                              // STS.128
            *apB = aB;
        }

        // ---- stage slabs for t+1 from regs, prefetch t+2
        if (t + 1 < NTIL) {
            __syncthreads();
            const int tasks1 = (88 - 8 * (t + 1)) * 4;
            #pragma unroll
            for (int k2 = 0; k2 < 2; k2++) {
                const int task = tid + k2 * BLOCK;
                if (task < tasks1) {
                    const int pr = task >> 2, q = task & 3;
                    ulonglong2* dst = reinterpret_cast<ulonglong2*>(Wx + pr * TT + 4 * q);
                    dst[0] = make_ulonglong2(pack2(wa[k2].x, wb[k2].x), pack2(wa[k2].y, wb[k2].y));
                    dst[1] = make_ulonglong2(pack2(wa[k2].z, wb[k2].z), pack2(wa[k2].w, wb[k2].w));
                }
            }
            if (tid < 240) Ws[tid] = tv;
            __syncthreads();

            if (t + 2 < NTIL) {
                const int cb2 = (t + 2) * TT, ce2 = cb2 + TT;
                const int tasks2 = (88 - 8 * (t + 2)) * 4;
                #pragma unroll
                for (int k2 = 0; k2 < 2; k2++) {
                    const int task = tid + k2 * BLOCK;
                    if (task < tasks2) {
                        const int pr = task >> 2, q = task & 3, c2 = ce2 + 2 * pr;
                        wa[k2] = __ldg(reinterpret_cast<const float4*>(W + (c2 - 1) * CCH + cb2 + 4 * q));
                        wb[k2] = __ldg(reinterpret_cast<const float4*>(W + c2 * CCH + cb2 + 4 * q));
                    }
                }
                if (tid < 240)
                    tv = __ldg(&W[(cb2 + (tid >> 4)) * CCH + cb2 + (tid & 15)]);
            }
        }
    }
}

extern "C" void kernel_launch(void* const* d_in, const int* in_sizes, int n_in,
                              void* d_out, int out_size)
{
    const float* x   = (const float*)d_in[0];
    const float* mix = (const float*)d_in[1];
    const float* W   = (const float*)d_in[2];
    const float* b   = (const float*)d_in[3];

    float* ybar_out = (float*)d_out;
    float* mix_out  = (float*)d_out + NCHW;

    const size_t smem_bytes = (size_t)(BLOCK * ACC_STRIDE + 88 * TT) * sizeof(u64)
                            + (240 + 191) * sizeof(float);
    cudaFuncSetAttribute(chan_deps_kernel,
                         cudaFuncAttributeMaxDynamicSharedMemorySize,
                         (int)smem_bytes);

    const int grid = NPIX / BLOCK;               // 128, single balanced wave
    chan_deps_kernel<<<grid, BLOCK, smem_bytes>>>(x, mix, W, b, ybar_out, mix_out);
}

// round 15
// speedup vs baseline: 1.0902x; 1.0898x over previous
#include <cuda_runtime.h>
#include <cuda_bf16.h>
#include <math.h>

// Shapes: x, mix: [8,192,64,64] fp32 ; W: [191,192] ; b: [191]
// Outputs: ybar then mix_out, each 6291456 floats, contiguous in d_out.
#define CCH   192
#define TT    16
#define NTIL  12
#define BLOCK 256              // 8 warps: 128 pixel-slots (2 adjacent px) x 2 roles
#define SLOTS 128
#define PIX_PER_BLOCK 256
#define NPIX  32768
#define NCHW  6291456
#define ACC_F4_STRIDE 97       // float4 stride/slot: conflict-free, 16B aligned

typedef unsigned long long u64;

__device__ __forceinline__ u64 pack2(float a, float b) {
    u64 r; asm("mov.b64 %0, {%1,%2};" : "=l"(r) : "f"(a), "f"(b)); return r;
}
__device__ __forceinline__ u64 fma2(u64 a, u64 b, u64 c) {
    u64 d; asm("fma.rn.f32x2 %0, %1, %2, %3;" : "=l"(d) : "l"(a), "l"(b), "l"(c)); return d;
}
__device__ __forceinline__ u64 add2(u64 a, u64 b) {
    u64 d; asm("add.rn.f32x2 %0, %1, %2;" : "=l"(d) : "l"(a), "l"(b)); return d;
}

// smem: acc 128*97*16 = 198656 B, Wx 88*16*8 = 11264 B, Wd 240*8 = 1920 B,
//       bs 191*4 = 764 B  -> 212604 B (~207.6 KB) < 227 KB
__global__ void __launch_bounds__(BLOCK, 1)
chan_deps_kernel(const float* __restrict__ x,
                 const float* __restrict__ mix,
                 const float* __restrict__ W,
                 const float* __restrict__ b,
                 float* __restrict__ ybar_out,
                 float* __restrict__ mix_out)
{
    extern __shared__ float smem[];
    float4* acc4 = reinterpret_cast<float4*>(smem);                  // [128][97]
    u64*    Wx   = reinterpret_cast<u64*>(smem + 4 * SLOTS * ACC_F4_STRIDE); // 88*16
    u64*    Wd   = Wx + 88 * TT;                                     // 240 dup pairs (tri)
    float*  bs   = reinterpret_cast<float*>(Wd + 240);               // 191

    const int tid  = threadIdx.x;
    const int slot = tid & (SLOTS - 1);
    const int role = tid >> 7;                                       // 0 or 1
    const int p0   = blockIdx.x * PIX_PER_BLOCK + 2 * slot;          // even pixel
    const int base = (((p0 >> 12) * CCH) << 12) + (p0 & 4095);

    float4* accp4 = acc4 + slot * ACC_F4_STRIDE;

    // zero accumulators (roles split the 96 used float4 of their slot)
    {
        const float4 z = make_float4(0.f, 0.f, 0.f, 0.f);
        #pragma unroll 8
        for (int k = role * 48; k < role * 48 + 48; k++) accp4[k] = z;
    }
    if (tid < CCH - 1) bs[tid] = __ldg(&b[tid]);

    // ---- direct-stage tile 0 slabs ----
    for (int k = tid; k < 88 * 4; k += BLOCK) {
        const int pr = k >> 2, q = k & 3, c2 = TT + 2 * pr, col = 4 * q;
        const float4 wa4 = __ldg(reinterpret_cast<const float4*>(W + (c2 - 1) * CCH + col));
        const float4 wb4 = __ldg(reinterpret_cast<const float4*>(W + c2 * CCH + col));
        ulonglong2* dst = reinterpret_cast<ulonglong2*>(Wx + pr * TT + col);
        dst[0] = make_ulonglong2(pack2(wa4.x, wb4.x), pack2(wa4.y, wb4.y));
        dst[1] = make_ulonglong2(pack2(wa4.z, wb4.z), pack2(wa4.w, wb4.w));
    }
    if (tid < 240) {
        const float v = __ldg(&W[(tid >> 4) * CCH + (tid & 15)]);
        Wd[tid] = pack2(v, v);
    }
    __syncthreads();

    // ---- prefetch tile 1 slabs into registers ----
    float4 wa[2], wb[2];
    float  tv;
    {
        const int cb = TT, ce = 2 * TT, tasks = (88 - 8) * 4;        // 320
        #pragma unroll
        for (int k2 = 0; k2 < 2; k2++) {
            const int task = tid + k2 * BLOCK;
            if (task < tasks) {
                const int pr = task >> 2, q = task & 3, c2 = ce + 2 * pr;
                wa[k2] = __ldg(reinterpret_cast<const float4*>(W + (c2 - 1) * CCH + cb + 4 * q));
                wb[k2] = __ldg(reinterpret_cast<const float4*>(W + c2 * CCH + cb + 4 * q));
            }
        }
        if (tid < 240) tv = __ldg(&W[(cb + (tid >> 4)) * CCH + cb + (tid & 15)]);
    }

    for (int t = 0; t < NTIL; t++) {
        const int cbase = t * TT;
        const int cend  = cbase + TT;
        const int pairs = 88 - 8 * t;                // multiple of 8; 0 at t=11

        // ---- x/mix for the adjacent pixel pair (LDG.64; both roles load)
        float2 xv[TT], mv[TT];
        #pragma unroll
        for (int i = 0; i < TT; i++) {
            const int gi = base + ((cbase + i) << 12);
            xv[i] = __ldg(reinterpret_cast<const float2*>(x + gi));
            mv[i] = __ldg(reinterpret_cast<const float2*>(mix + gi));
        }

        // ---- sequential in-tile recurrence (redundant across roles; bit-identical)
        float part0[TT], part1[TT];
        #pragma unroll
        for (int i = 0; i < TT; i++) { part0[i] = 0.f; part1[i] = 0.f; }

        u64 yd0[TT], yd1[TT];
        float4 a4;
        #pragma unroll
        for (int i = 0; i < TT; i++) {
            const int c = cbase + i;
            if ((i & 1) == 0) a4 = accp4[c >> 1];    // LDS.128, 2 ch x 2 px
            float m0, m1;
            if (i == 0 && t == 0) {                  // channel 0: no conv/bias
                m0 = mv[0].x;
                m1 = mv[0].y;
            } else {
                const float a0 = (i & 1) ? a4.y : a4.x;
                const float a1 = (i & 1) ? a4.w : a4.z;
                const float bb = bs[c - 1];
                m0 = a0 + bb + mv[i].x + part0[i];
                m1 = a1 + bb + mv[i].y + part1[i];
            }
            const float y0 = rintf(xv[i].x - m0) + m0;   // half-to-even = jnp.round
            const float y1 = rintf(xv[i].y - m1) + m1;
            yd0[i] = pack2(y0, y0);
            yd1[i] = pack2(y1, y1);
            if (role == 0) {                         // one role owns the stores
                const int gi = base + (c << 12);
                *reinterpret_cast<float2*>(ybar_out + gi) = make_float2(y0, y1);
                *reinterpret_cast<float2*>(mix_out  + gi) = make_float2(m0, m1);
            }
            #pragma unroll
            for (int i2 = i + 1; i2 < TT; i2++) {
                const float w = reinterpret_cast<const float*>(Wd)[2 * ((i2 - 1) * TT + i)];
                part0[i2] = fmaf(w, y0, part0[i2]);
                part1[i2] = fmaf(w, y1, part1[i2]);
            }
        }

        // ---- cross-tile rank-16 update: roles split the pr range (disjoint acc)
        const int kb   = cend >> 1;                  // even -> 16B-aligned pairs
        const int half = pairs >> 1;                 // even (pairs multiple of 8)
        const int prLo = role ? half  : 0;
        const int prHi = role ? pairs : half;
        for (int pr = prLo; pr < prHi; pr += 2) {
            const ulonglong2* wpA = reinterpret_cast<const ulonglong2*>(Wx + (pr << 4));
            const ulonglong2* wpB = reinterpret_cast<const ulonglong2*>(Wx + ((pr + 1) << 4));
            u64 sA0 = 0, sA1 = 0, sB0 = 0, sB1 = 0;
            #pragma unroll
            for (int h = 0; h < 8; h++) {
                const ulonglong2 A = wpA[h];
                sA0 = fma2(A.x, yd0[2 * h], sA0); sA0 = fma2(A.y, yd0[2 * h + 1], sA0);
                sA1 = fma2(A.x, yd1[2 * h], sA1); sA1 = fma2(A.y, yd1[2 * h + 1], sA1);
                const ulonglong2 B = wpB[h];
                sB0 = fma2(B.x, yd0[2 * h], sB0); sB0 = fma2(B.y, yd0[2 * h + 1], sB0);
                sB1 = fma2(B.x, yd1[2 * h], sB1); sB1 = fma2(B.y, yd1[2 * h + 1], sB1);
            }
            float4 aA = accp4[kb + pr];
            float4 aB = accp4[kb + pr + 1];
            u64* auA = reinterpret_cast<u64*>(&aA);
            u64* auB = reinterpret_cast<u64*>(&aB);
            auA[0] = add2(auA[0], sA0); auA[1] = add2(auA[1], sA1);
            auB[0] = add2(auB[0], sB0); auB[1] = add2(auB[1], sB1);
            accp4[kb + pr]     = aA;
            accp4[kb + pr + 1] = aB;
        }

        // ---- stage slabs for t+1 from regs, prefetch t+2
        if (t + 1 < NTIL) {
            __syncthreads();                         // cross-tile writes done (both roles)
            const int tasks1 = (88 - 8 * (t + 1)) * 4;
            #pragma unroll
            for (int k2 = 0; k2 < 2; k2++) {
                const int task = tid + k2 * BLOCK;
                if (task < tasks1) {
                    const int pr = task >> 2, q = task & 3;
                    ulonglong2* dst = reinterpret_cast<ulonglong2*>(Wx + pr * TT + 4 * q);
                    dst[0] = make_ulonglong2(pack2(wa[k2].x, wb[k2].x), pack2(wa[k2].y, wb[k2].y));
                    dst[1] = make_ulonglong2(pack2(wa[k2].z, wb[k2].z), pack2(wa[k2].w, wb[k2].w));
                }
            }
            if (tid < 240) Wd[tid] = pack2(tv, tv);
            __syncthreads();

            if (t + 2 < NTIL) {
                const int cb2 = (t + 2) * TT, ce2 = cb2 + TT;
                const int tasks2 = (88 - 8 * (t + 2)) * 4;
                #pragma unroll
                for (int k2 = 0; k2 < 2; k2++) {
                    const int task = tid + k2 * BLOCK;
                    if (task < tasks2) {
                        const int pr = task >> 2, q = task & 3, c2 = ce2 + 2 * pr;
                        wa[k2] = __ldg(reinterpret_cast<const float4*>(W + (c2 - 1) * CCH + cb2 + 4 * q));
                        wb[k2] = __ldg(reinterpret_cast<const float4*>(W + c2 * CCH + cb2 + 4 * q));
                    }
                }
                if (tid < 240)
                    tv = __ldg(&W[(cb2 + (tid >> 4)) * CCH + cb2 + (tid & 15)]);
            }
        }
    }
}

extern "C" void kernel_launch(void* const* d_in, const int* in_sizes, int n_in,
                              void* d_out, int out_size)
{
    const float* x   = (const float*)d_in[0];
    const float* mix = (const float*)d_in[1];
    const float* W   = (const float*)d_in[2];
    const float* b   = (const float*)d_in[3];

    float* ybar_out = (float*)d_out;
    float* mix_out  = (float*)d_out + NCHW;

    const size_t smem_bytes = (size_t)(4 * SLOTS * ACC_F4_STRIDE) * sizeof(float)
                            + (88 * TT + 240) * sizeof(u64)
                            + 191 * sizeof(float);
    cudaFuncSetAttribute(chan_deps_kernel,
                         cudaFuncAttributeMaxDynamicSharedMemorySize,
                         (int)smem_bytes);

    const int grid = NPIX / PIX_PER_BLOCK;           // 128, single balanced wave
    chan_deps_kernel<<<grid, BLOCK, smem_bytes>>>(x, mix, W, b, ybar_out, mix_out);
}

// round 16
// speedup vs baseline: 1.3310x; 1.2209x over previous
#include <cuda_runtime.h>
#include <cuda_bf16.h>
#include <math.h>

// Shapes: x, mix: [8,192,64,64] fp32 ; W: [191,192] ; b: [191]
// Outputs: ybar then mix_out, each 6291456 floats, contiguous in d_out.
//
// Warp-specialized pipeline:
//   R-group (tid 0..255):  per-pixel serial recurrence (1 px/thread), output
//                          stores, W-slab prefetch (regs) + staging (phase B).
//   G-group (tid 256..511): cross-tile rank-16 FFMA2 updates; 128 slots
//                          (2 adjacent px) x 2 roles (half the rows each).
// Per tile t: [A: rec(t) || lazy(t-1)] sync [B: urgent(t) || stage W(t+1)] sync
//   lazy(t-1) writes acc rows of tiles >= t+1; rec(t) reads rows of tile t
//   -> disjoint. urgent(t) finalizes tile t+1 rows before rec(t+1).
#define CCH   192
#define TT    16
#define NTIL  12
#define BLOCK 512
#define RTH   256             // R-threads (= pixels per block)
#define SLOTS 128             // G pixel-pair slots
#define NPIX  32768
#define NCHW  6291456
#define ACC_F4_STRIDE 97      // float4 stride/slot: conflict-free, 16B aligned

typedef unsigned long long u64;

__device__ __forceinline__ u64 pack2(float a, float b) {
    u64 r; asm("mov.b64 %0, {%1,%2};" : "=l"(r) : "f"(a), "f"(b)); return r;
}
__device__ __forceinline__ u64 fma2(u64 a, u64 b, u64 c) {
    u64 d; asm("fma.rn.f32x2 %0, %1, %2, %3;" : "=l"(d) : "l"(a), "l"(b), "l"(c)); return d;
}
__device__ __forceinline__ u64 add2(u64 a, u64 b) {
    u64 d; asm("add.rn.f32x2 %0, %1, %2;" : "=l"(d) : "l"(a), "l"(b)); return d;
}

// One cross update for channel-pair rows (pr, pr+1). Bit-identical order to R15.
__device__ __forceinline__ void cross_pair(const u64* wxRow0, const u64* wxRow1,
                                           const u64* yd0, const u64* yd1,
                                           float4* a0p, float4* a1p)
{
    const ulonglong2* wpA = reinterpret_cast<const ulonglong2*>(wxRow0);
    const ulonglong2* wpB = reinterpret_cast<const ulonglong2*>(wxRow1);
    u64 sA0 = 0, sA1 = 0, sB0 = 0, sB1 = 0;
    #pragma unroll
    for (int h = 0; h < 8; h++) {
        const ulonglong2 A = wpA[h];
        sA0 = fma2(A.x, yd0[2 * h], sA0); sA0 = fma2(A.y, yd0[2 * h + 1], sA0);
        sA1 = fma2(A.x, yd1[2 * h], sA1); sA1 = fma2(A.y, yd1[2 * h + 1], sA1);
        const ulonglong2 B = wpB[h];
        sB0 = fma2(B.x, yd0[2 * h], sB0); sB0 = fma2(B.y, yd0[2 * h + 1], sB0);
        sB1 = fma2(B.x, yd1[2 * h], sB1); sB1 = fma2(B.y, yd1[2 * h + 1], sB1);
    }
    float4 aA = *a0p;
    float4 aB = *a1p;
    u64* auA = reinterpret_cast<u64*>(&aA);
    u64* auB = reinterpret_cast<u64*>(&aB);
    auA[0] = add2(auA[0], sA0); auA[1] = add2(auA[1], sA1);
    auB[0] = add2(auB[0], sB0); auB[1] = add2(auB[1], sB1);
    *a0p = aA;
    *a1p = aB;
}

// smem: acc 128*97*16 = 198656, Wx x2 = 22528, Wd 960, bs 764 -> 222908 B
__global__ void __launch_bounds__(BLOCK, 1)
chan_deps_kernel(const float* __restrict__ x,
                 const float* __restrict__ mix,
                 const float* __restrict__ W,
                 const float* __restrict__ b,
                 float* __restrict__ ybar_out,
                 float* __restrict__ mix_out)
{
    extern __shared__ float smem[];
    float4* acc4  = reinterpret_cast<float4*>(smem);                      // [128][97]
    u64*    WxBuf = reinterpret_cast<u64*>(smem + 4 * SLOTS * ACC_F4_STRIDE); // 2x 88*16
    float*  Wd    = reinterpret_cast<float*>(WxBuf + 2 * 88 * TT);        // 240 tri
    float*  bs    = Wd + 240;                                             // 191 bias

    const int tid = threadIdx.x;

    // zero accumulators (padding too; harmless)
    {
        const float4 z = make_float4(0.f, 0.f, 0.f, 0.f);
        for (int k = tid; k < SLOTS * ACC_F4_STRIDE; k += BLOCK) acc4[k] = z;
    }
    if (tid < CCH - 1) bs[tid] = __ldg(&b[tid]);

    // stage tile-0 slabs (Wx buf0, Wd)
    for (int k = tid; k < 88 * 4; k += BLOCK) {
        const int pr = k >> 2, q = k & 3, c2 = TT + 2 * pr, col = 4 * q;
        const float4 a4 = __ldg(reinterpret_cast<const float4*>(W + (c2 - 1) * CCH + col));
        const float4 b4 = __ldg(reinterpret_cast<const float4*>(W + c2 * CCH + col));
        ulonglong2* dst = reinterpret_cast<ulonglong2*>(WxBuf + pr * TT + col);
        dst[0] = make_ulonglong2(pack2(a4.x, b4.x), pack2(a4.y, b4.y));
        dst[1] = make_ulonglong2(pack2(a4.z, b4.z), pack2(a4.w, b4.w));
    }
    if (tid < 240) Wd[tid] = __ldg(&W[(tid >> 4) * CCH + (tid & 15)]);
    __syncthreads();

    if (tid < RTH) {
        // ================= R-group: recurrence =================
        const int p    = blockIdx.x * RTH + tid;                 // 1 pixel/thread
        const int base = (((p >> 12) * CCH) << 12) + (p & 4095);
        const int slot = tid >> 1, half = tid & 1;
        const float* accRow = reinterpret_cast<const float*>(acc4 + slot * ACC_F4_STRIDE)
                            + half * 2;

        float xv[TT], mv[TT], xn[TT], mn[TT];
        #pragma unroll
        for (int i = 0; i < TT; i++) {
            xv[i] = __ldg(&x[base + (i << 12)]);
            mv[i] = __ldg(&mix[base + (i << 12)]);
        }

        // prefetch tile-1 W slabs into registers
        float4 wpa[2], wpb[2];
        float  wdv = 0.f;
        {
            const int cb = TT, ce = 2 * TT, tasks = (88 - 8) * 4;  // 320
            #pragma unroll
            for (int k2 = 0; k2 < 2; k2++) {
                const int task = tid + k2 * RTH;
                if (task < tasks) {
                    const int pr = task >> 2, q = task & 3, c2 = ce + 2 * pr;
                    wpa[k2] = __ldg(reinterpret_cast<const float4*>(W + (c2 - 1) * CCH + cb + 4 * q));
                    wpb[k2] = __ldg(reinterpret_cast<const float4*>(W + c2 * CCH + cb + 4 * q));
                }
            }
            if (tid < 240) wdv = __ldg(&W[(cb + (tid >> 4)) * CCH + cb + (tid & 15)]);
        }

        for (int t = 0; t < NTIL; t++) {
            const int cbase = t * TT;

            // phase A: issue x/mix prefetch for t+1, then recurrence(t)
            if (t + 1 < NTIL) {
                #pragma unroll
                for (int i = 0; i < TT; i++) {
                    const int gi = base + ((cbase + TT + i) << 12);
                    xn[i] = __ldg(&x[gi]);
                    mn[i] = __ldg(&mix[gi]);
                }
            }
            float part[TT];
            #pragma unroll
            for (int i = 0; i < TT; i++) part[i] = 0.f;
            float2 av = make_float2(0.f, 0.f);
            #pragma unroll
            for (int i = 0; i < TT; i++) {
                const int c = cbase + i;
                if ((i & 1) == 0)
                    av = *reinterpret_cast<const float2*>(accRow + (c >> 1) * 4);
                float m;
                if (i == 0 && t == 0) {                    // channel 0: no conv/bias
                    m = mv[0];
                } else {
                    const float a = (i & 1) ? av.y : av.x;
                    m = a + bs[c - 1] + mv[i] + part[i];
                }
                const float y = rintf(xv[i] - m) + m;      // half-to-even = jnp.round
                const int gi = base + (c << 12);
                ybar_out[gi] = y;
                mix_out[gi]  = m;
                #pragma unroll
                for (int i2 = i + 1; i2 < TT; i2++)
                    part[i2] = fmaf(Wd[(i2 - 1) * TT + i], y, part[i2]);
            }
            __syncthreads();                               // A -> B

            // phase B: stage W slabs for t+1 (G reads them at urgent(t+1)/lazy(t+1)),
            //          prefetch t+2, rotate x/mix buffers
            if (t + 1 < NTIL) {
                u64* WxN = WxBuf + ((t + 1) & 1) * 88 * TT;
                const int tasks1 = (88 - 8 * (t + 1)) * 4;
                #pragma unroll
                for (int k2 = 0; k2 < 2; k2++) {
                    const int task = tid + k2 * RTH;
                    if (task < tasks1) {
                        const int pr = task >> 2, q = task & 3;
                        ulonglong2* dst = reinterpret_cast<ulonglong2*>(WxN + pr * TT + 4 * q);
                        dst[0] = make_ulonglong2(pack2(wpa[k2].x, wpb[k2].x),
                                                 pack2(wpa[k2].y, wpb[k2].y));
                        dst[1] = make_ulonglong2(pack2(wpa[k2].z, wpb[k2].z),
                                                 pack2(wpa[k2].w, wpb[k2].w));
                    }
                }
                if (tid < 240) Wd[tid] = wdv;
                if (t + 2 < NTIL) {
                    const int cb2 = (t + 2) * TT, ce2 = cb2 + TT;
                    const int tasks2 = (88 - 8 * (t + 2)) * 4;
                    #pragma unroll
                    for (int k2 = 0; k2 < 2; k2++) {
                        const int task = tid + k2 * RTH;
                        if (task < tasks2) {
                            const int pr = task >> 2, q = task & 3, c2 = ce2 + 2 * pr;
                            wpa[k2] = __ldg(reinterpret_cast<const float4*>(W + (c2 - 1) * CCH + cb2 + 4 * q));
                            wpb[k2] = __ldg(reinterpret_cast<const float4*>(W + c2 * CCH + cb2 + 4 * q));
                        }
                    }
                    if (tid < 240)
                        wdv = __ldg(&W[(cb2 + (tid >> 4)) * CCH + cb2 + (tid & 15)]);
                }
                #pragma unroll
                for (int i = 0; i < TT; i++) { xv[i] = xn[i]; mv[i] = mn[i]; }
            }
            __syncthreads();                               // B -> A(next)
        }
    } else {
        // ================= G-group: cross-tile GEMM =================
        const int gt   = tid - RTH;
        const int slot = gt & (SLOTS - 1);
        const int role = gt >> 7;                          // 0 or 1
        const int p0   = blockIdx.x * RTH + 2 * slot;
        const int base = (((p0 >> 12) * CCH) << 12) + (p0 & 4095);
        float4* accp4  = acc4 + slot * ACC_F4_STRIDE;

        u64 yd0[TT], yd1[TT];
        #pragma unroll
        for (int i = 0; i < TT; i++) { yd0[i] = 0; yd1[i] = 0; }

        for (int t = 0; t < NTIL; t++) {
            // phase A: lazy(t-1) — rows of tiles >= t+1 (disjoint from rec(t) reads)
            if (t > 0) {
                const int pairsP  = 88 - 8 * (t - 1);
                const int lazyCnt = pairsP - 8;            // multiple of 8, >= 0
                if (lazyCnt > 0) {
                    const int halfc = lazyCnt >> 1;        // even
                    const int lo = 8 + role * halfc;
                    const int hi = lo + halfc;
                    const u64* WxP = WxBuf + ((t - 1) & 1) * 88 * TT;
                    const int kb = 8 * t;                  // cend(t-1)/2
                    for (int pr = lo; pr < hi; pr += 2)
                        cross_pair(WxP + (pr << 4), WxP + ((pr + 1) << 4),
                                   yd0, yd1, accp4 + kb + pr, accp4 + kb + pr + 1);
                }
            }
            __syncthreads();                               // A -> B

            // phase B: reload y(t) from ybar (block-visible after sync), urgent(t)
            const int pairs = 88 - 8 * t;
            if (pairs > 0) {
                #pragma unroll
                for (int i = 0; i < TT; i++) {
                    const float2 yy = *reinterpret_cast<const float2*>(
                        ybar_out + base + ((t * TT + i) << 12));
                    yd0[i] = pack2(yy.x, yy.x);
                    yd1[i] = pack2(yy.y, yy.y);
                }
                const u64* WxT = WxBuf + (t & 1) * 88 * TT;
                const int kb = 8 * (t + 1);                // cend(t)/2
                const int lo = role * 4, hi = lo + 4;      // urgent rows 0..7 split
                for (int pr = lo; pr < hi; pr += 2)
                    cross_pair(WxT + (pr << 4), WxT + ((pr + 1) << 4),
                               yd0, yd1, accp4 + kb + pr, accp4 + kb + pr + 1);
            }
            __syncthreads();                               // B -> A(next)
        }
    }
}

extern "C" void kernel_launch(void* const* d_in, const int* in_sizes, int n_in,
                              void* d_out, int out_size)
{
    const float* x   = (const float*)d_in[0];
    const float* mix = (const float*)d_in[1];
    const float* W   = (const float*)d_in[2];
    const float* b   = (const float*)d_in[3];

    float* ybar_out = (float*)d_out;
    float* mix_out  = (float*)d_out + NCHW;

    const size_t smem_bytes = (size_t)(4 * SLOTS * ACC_F4_STRIDE) * sizeof(float)
                            + (size_t)(2 * 88 * TT) * sizeof(u64)
                            + (240 + 191) * sizeof(float);     // 222,908 B
    cudaFuncSetAttribute(chan_deps_kernel,
                         cudaFuncAttributeMaxDynamicSharedMemorySize,
                         (int)smem_bytes);

    const int grid = NPIX / RTH;                 // 128, single balanced wave
    chan_deps_kernel<<<grid, BLOCK, smem_bytes>>>(x, mix, W, b, ybar_out, mix_out);
}